// round 5
// baseline (speedup 1.0000x reference)
#include <cuda_runtime.h>
#include <cuda_bf16.h>

// Scratch for per-voxel results (device globals: allocation-free).
#define MAXV 262144
__device__ float     g_val[MAXV * 16];       // 16.8 MB
__device__ long long g_flat[MAXV];

#define ZCHUNK 32   // float4 stores per zero-role thread

// ---------------------------------------------------------------------------
// Fused kernel: interleaved zero-role blocks (stream 537MB of zeros to d_out)
// and MLP-role blocks (per-voxel PointNet -> scratch). Roles interleaved by
// blockIdx so both kinds run concurrently across the chip: the store-bound
// zero pass hides the latency/compute-bound MLP.
//
// Centered-weight trick: layernorm mean commutes with the preceding linear
// layer, so with W1c = W1 - rowmean(W1), b1c = b1 - mean(b1):
//   yc = x@W1c + b1c  is exactly (y - mean(y)); var = mean(yc^2).
// Same for the second LN via W2c/b2c. Saves the mean reduction and all
// (y - mu) subtractions.
// ---------------------------------------------------------------------------
__global__ __launch_bounds__(256, 3)
void fused_zero_mlp(const float* __restrict__ features,
                    const int*   __restrict__ num_points,
                    const int*   __restrict__ coords,
                    const float* __restrict__ W1,  const float* __restrict__ b1,
                    const float* __restrict__ g1,  const float* __restrict__ be1,
                    const float* __restrict__ W2,  const float* __restrict__ b2,
                    const float* __restrict__ g2,  const float* __restrict__ be2,
                    const int*   __restrict__ p_gh,
                    const int*   __restrict__ p_gw,
                    const int*   __restrict__ p_gz,
                    float*       __restrict__ out,
                    long n4, int ntail,
                    int MB, int STRIDE,
                    int V, int P, long out_elems, long stride_fallback)
{
    const int bid = blockIdx.x;
    const int tid = threadIdx.x;

    int mlp_id = -1;
    if ((bid % STRIDE) == 0 && (bid / STRIDE) < MB) mlp_id = bid / STRIDE;

    if (mlp_id < 0) {
        // ---------------- zero role ----------------
        // rank among zero blocks = bid minus #MLP blocks at index <= bid
        int cnt = (bid + STRIDE - 1) / STRIDE;   // multiples of STRIDE in [0, bid)... see note
        // multiples of STRIDE strictly below bid, capped at MB:
        if (cnt > MB) cnt = MB;
        long z = (long)bid - cnt;

        float4* o4 = reinterpret_cast<float4*>(out);
        const long base = z * (long)(256 * ZCHUNK);
        const float4 zero4 = make_float4(0.f, 0.f, 0.f, 0.f);
#pragma unroll
        for (int i = 0; i < ZCHUNK; i++) {
            long idx = base + (long)i * 256 + tid;
            if (idx < n4) o4[idx] = zero4;
        }
        if (z == 0 && tid == 0) {
            for (int t = 0; t < ntail; t++) out[n4 * 4 + t] = 0.f;
        }
        return;
    }

    // ---------------- MLP role ----------------
    __shared__ float sW1c[64], sW2c[256];
    __shared__ float sb1c[16], sg1[16], sbe1[16];
    __shared__ float sb2c[16], sg2[16], sbe2[16];

    if (tid < 64) {                       // W1 is [4][16]; center each row over its 16 outputs
        int row = tid >> 4;
        float s = 0.f;
        for (int k = 0; k < 16; k++) s += W1[row * 16 + k];
        sW1c[tid] = W1[tid] - s * 0.0625f;
    }
    {                                     // W2 is [16][16]; center each row over its 16 outputs
        int row = tid >> 4;
        float s = 0.f;
        for (int k = 0; k < 16; k++) s += W2[row * 16 + k];
        sW2c[tid] = W2[tid] - s * 0.0625f;
    }
    if (tid < 16) {
        float s1 = 0.f, s2 = 0.f;
        for (int k = 0; k < 16; k++) { s1 += b1[k]; s2 += b2[k]; }
        sb1c[tid] = b1[tid] - s1 * 0.0625f;
        sb2c[tid] = b2[tid] - s2 * 0.0625f;
        sg1[tid] = g1[tid];  sbe1[tid] = be1[tid];
        sg2[tid] = g2[tid];  sbe2[tid] = be2[tid];
    }
    __syncthreads();

    const int v = mlp_id * 256 + tid;
    if (v >= V || v >= MAXV) return;

    int n = num_points[v];
    if (n < 0) n = 0;
    if (n > P) n = P;

    const float4* f = reinterpret_cast<const float4*>(features) + (size_t)v * P;

    float acc[16];
#pragma unroll
    for (int j = 0; j < 16; j++) acc[j] = 0.f;

    // Manually pipelined point loop: load next point while computing current.
    float4 x = (n > 0) ? f[0] : make_float4(0.f, 0.f, 0.f, 0.f);
#pragma unroll 1
    for (int p = 0; p < n; p++) {
        float4 xn = x;
        if (p + 1 < n) xn = f[p + 1];

        float yc[16];
        float var = 0.f;
#pragma unroll
        for (int j = 0; j < 16; j++) {
            float t = fmaf(x.x, sW1c[j],      sb1c[j]);
            t       = fmaf(x.y, sW1c[16 + j], t);
            t       = fmaf(x.z, sW1c[32 + j], t);
            t       = fmaf(x.w, sW1c[48 + j], t);
            yc[j]   = t;
            var     = fmaf(t, t, var);
        }
        const float inv = rsqrtf(fmaf(var, 0.0625f, 1e-5f));
#pragma unroll
        for (int j = 0; j < 16; j++) {
            float h = fmaf(yc[j] * inv, sg1[j], sbe1[j]);
            acc[j] += fmaxf(h, 0.f);
        }
        x = xn;
    }

    // Second linear with centered weights: x2c is already mean-free.
    float x2[16];
    const float fn = (float)n;
#pragma unroll
    for (int i = 0; i < 16; i++) x2[i] = fn * sb2c[i];
#pragma unroll
    for (int j = 0; j < 16; j++) {
        const float a = acc[j];
#pragma unroll
        for (int i = 0; i < 16; i++) x2[i] = fmaf(a, sW2c[j * 16 + i], x2[i]);
    }
    float var = 0.f;
#pragma unroll
    for (int i = 0; i < 16; i++) var = fmaf(x2[i], x2[i], var);
    const float inv = rsqrtf(fmaf(var, 0.0625f, 1e-5f));

    // Scatter destination (mode='drop': per-dim bounds checks)
    long flat;
    bool ok = true;
    if (p_gh != nullptr) {
        const int GH = *p_gh, GW = *p_gw, GZ = *p_gz;
        const int b  = coords[4 * v + 0];
        const int ix = coords[4 * v + 1];
        const int iy = coords[4 * v + 2];
        const int iz = coords[4 * v + 3];
        const long B = out_elems / ((long)GH * GW * GZ * 16);
        ok = (b >= 0 && b < B && ix >= 0 && ix < GH &&
              iy >= 0 && iy < GW && iz >= 0 && iz < GZ);
        flat = (((long)b * GH + ix) * GW + iy) * (long)GZ + iz;
    } else {
        flat = (long)v * stride_fallback;
    }
    const long off = flat * 16;
    if (off < 0 || off + 16 > out_elems) ok = false;

    g_flat[v] = ok ? off : -1;

    float4* s4 = reinterpret_cast<float4*>(g_val + (size_t)v * 16);
#pragma unroll
    for (int q = 0; q < 4; q++) {
        float4 r;
        r.x = fmaf(x2[4 * q + 0] * inv, sg2[4 * q + 0], sbe2[4 * q + 0]);
        r.y = fmaf(x2[4 * q + 1] * inv, sg2[4 * q + 1], sbe2[4 * q + 1]);
        r.z = fmaf(x2[4 * q + 2] * inv, sg2[4 * q + 2], sbe2[4 * q + 2]);
        r.w = fmaf(x2[4 * q + 3] * inv, sg2[4 * q + 3], sbe2[4 * q + 3]);
        s4[q] = r;
    }
}

// ---------------------------------------------------------------------------
// Scatter kernel: 4 threads per voxel, copy scratch -> dense output.
// Runs after all zeroing completes (same stream) — no race.
// ---------------------------------------------------------------------------
__global__ __launch_bounds__(256)
void scatter_kernel(float* __restrict__ out, int V)
{
    const int t = blockIdx.x * 256 + threadIdx.x;
    const int v = t >> 2;
    const int q = t & 3;
    if (v >= V) return;
    const long off = g_flat[v];
    if (off < 0) return;
    const float4 r = reinterpret_cast<const float4*>(g_val + (size_t)v * 16)[q];
    reinterpret_cast<float4*>(out + off)[q] = r;
}

extern "C" void kernel_launch(void* const* d_in, const int* in_sizes, int n_in,
                              void* d_out, int out_size)
{
    // metadata order: features, num_points, coords, W1, b1, g1, be1,
    //                 W2, b2, g2, be2, batch_size, grid_h, grid_w, grid_z
    const float* features   = (const float*)d_in[0];
    const int*   num_points = (const int*)  d_in[1];
    const int*   coords     = (const int*)  d_in[2];
    const float* W1  = (const float*)d_in[3];
    const float* b1  = (const float*)d_in[4];
    const float* g1  = (const float*)d_in[5];
    const float* be1 = (const float*)d_in[6];
    const float* W2  = (const float*)d_in[7];
    const float* b2  = (const float*)d_in[8];
    const float* g2  = (const float*)d_in[9];
    const float* be2 = (const float*)d_in[10];

    const int* p_gh = nullptr;
    const int* p_gw = nullptr;
    const int* p_gz = nullptr;
    if (n_in >= 15) {
        p_gh = (const int*)d_in[12];
        p_gw = (const int*)d_in[13];
        p_gz = (const int*)d_in[14];
    }

    const int V  = in_sizes[1];                 // num_points length
    const int H  = in_sizes[4];                 // b1 length (16)
    const int IN = in_sizes[3] / H;             // W1 rows (4)
    const int P  = (in_sizes[0] / V) / IN;      // points per voxel (32)

    float* out = (float*)d_out;
    const long out_elems = (long)out_size;
    const long stride_fallback = (out_elems / 16) / (long)V;

    const long n4    = out_elems / 4;
    const int  ntail = (int)(out_elems % 4);

    const int Vc = (V < MAXV) ? V : MAXV;
    const int MB = (Vc + 255) / 256;                                  // MLP blocks
    const long ZBl = (n4 + (long)(256 * ZCHUNK) - 1) / (256 * ZCHUNK);// zero blocks
    const int ZB = (int)ZBl;
    const int T  = ZB + MB;
    int STRIDE = T / MB;
    if (STRIDE < 1) STRIDE = 1;

    fused_zero_mlp<<<T, 256>>>(
        features, num_points, coords,
        W1, b1, g1, be1, W2, b2, g2, be2,
        p_gh, p_gw, p_gz,
        out, n4, ntail, MB, STRIDE,
        V, P, out_elems, stride_fallback);

    const int sthreads = V * 4;
    const int sblocks  = (sthreads + 255) / 256;
    scatter_kernel<<<sblocks, 256>>>(out, V);
}

// round 14
// speedup vs baseline: 2.1390x; 2.1390x over previous
#include <cuda_runtime.h>
#include <cuda_bf16.h>

// ---------------------------------------------------------------------------
// Quad-per-voxel PointNet MLP + direct scatter.
//
// 4 consecutive threads (a "quad") cooperate on one voxel; each thread owns
// 4 of the 16 hidden/output channels (~40 regs/thread vs ~170 for the
// thread-per-voxel version -> high occupancy, no spills).
//
// Shuffle-mask fix (round-10 NaN): the point loop's trip count n varies per
// quad within a warp, so in-loop shuffles MUST use a quad-local member mask
// (0xF << (lane & ~3)) — n is uniform within a quad, so quad partners are
// always converged; naming the whole warp while some lanes have exited the
// loop is UB and produced the NaN.
//
// Centered-weight trick: layernorm mean commutes with the preceding linear
// layer. With W1c = W1 - rowmean(W1), b1c = b1 - mean(b1):
//   yc = x@W1c + b1c  is exactly (y - mean(y)); var = mean(yc^2).
// Same for the second LN via W2c/b2c. No mean reductions needed.
//
// Scatter writes go straight to the dense output; the preceding memset on the
// same stream orders before this kernel.
// ---------------------------------------------------------------------------
__global__ __launch_bounds__(256)
void voxel_mlp_quad(const float* __restrict__ features,
                    const int*   __restrict__ num_points,
                    const int*   __restrict__ coords,
                    const float* __restrict__ W1,  const float* __restrict__ b1,
                    const float* __restrict__ g1,  const float* __restrict__ be1,
                    const float* __restrict__ W2,  const float* __restrict__ b2,
                    const float* __restrict__ g2,  const float* __restrict__ be2,
                    const int*   __restrict__ p_gh,
                    const int*   __restrict__ p_gw,
                    const int*   __restrict__ p_gz,
                    float*       __restrict__ out,
                    int V, int P, long out_elems, long stride_fallback)
{
    __shared__ float sW1c[64], sW2c[256];
    __shared__ float sb1c[16], sg1[16], sbe1[16];
    __shared__ float sb2c[16], sg2[16], sbe2[16];

    const int tid = threadIdx.x;

    // Stage centered weights in shared.
    if (tid < 64) {                       // W1 [4][16]: center each row over 16 outputs
        const int row = tid >> 4;
        float s = 0.f;
#pragma unroll
        for (int k = 0; k < 16; k++) s += W1[row * 16 + k];
        sW1c[tid] = W1[tid] - s * 0.0625f;
    }
    {                                     // W2 [16][16]: center each row
        const int row = tid >> 4;
        float s = 0.f;
#pragma unroll
        for (int k = 0; k < 16; k++) s += W2[row * 16 + k];
        sW2c[tid] = W2[tid] - s * 0.0625f;
    }
    if (tid < 16) {
        float s1 = 0.f, s2 = 0.f;
#pragma unroll
        for (int k = 0; k < 16; k++) { s1 += b1[k]; s2 += b2[k]; }
        sb1c[tid] = b1[tid] - s1 * 0.0625f;
        sb2c[tid] = b2[tid] - s2 * 0.0625f;
        sg1[tid] = g1[tid];  sbe1[tid] = be1[tid];
        sg2[tid] = g2[tid];  sbe2[tid] = be2[tid];
    }
    __syncthreads();

    const int q        = tid & 3;              // quad lane: channels [4q, 4q+4)
    const int lane     = tid & 31;
    const int quadbase = lane & ~3;            // first lane of this quad in warp
    const unsigned QMASK = 0xFu << quadbase;   // quad-local member mask

    const int vraw  = blockIdx.x * 64 + (tid >> 2);
    const bool live = (vraw < V);
    const int v     = live ? vraw : (V - 1);   // whole quad shares vraw -> quads
                                               // are entirely live or entirely dead

    int n = num_points[v];
    if (n < 0) n = 0;
    if (n > P) n = P;

    const float4* f = reinterpret_cast<const float4*>(features) + (size_t)v * P;
    const int ch = q * 4;                 // first owned channel

    float acc0 = 0.f, acc1 = 0.f, acc2 = 0.f, acc3 = 0.f;

    // Pipelined point loop: prefetch next point while computing current.
    float4 x = (n > 0) ? f[0] : make_float4(0.f, 0.f, 0.f, 0.f);
#pragma unroll 1
    for (int p = 0; p < n; p++) {
        float4 xn = x;
        if (p + 1 < n) xn = f[p + 1];

        // 4 owned channels of yc = x@W1c + b1c  (already mean-free)
        float y0, y1, y2, y3;
        {
            float t;
            t  = fmaf(x.x, sW1c[ch + 0],      sb1c[ch + 0]);
            t  = fmaf(x.y, sW1c[16 + ch + 0], t);
            t  = fmaf(x.z, sW1c[32 + ch + 0], t);
            y0 = fmaf(x.w, sW1c[48 + ch + 0], t);
            t  = fmaf(x.x, sW1c[ch + 1],      sb1c[ch + 1]);
            t  = fmaf(x.y, sW1c[16 + ch + 1], t);
            t  = fmaf(x.z, sW1c[32 + ch + 1], t);
            y1 = fmaf(x.w, sW1c[48 + ch + 1], t);
            t  = fmaf(x.x, sW1c[ch + 2],      sb1c[ch + 2]);
            t  = fmaf(x.y, sW1c[16 + ch + 2], t);
            t  = fmaf(x.z, sW1c[32 + ch + 2], t);
            y2 = fmaf(x.w, sW1c[48 + ch + 2], t);
            t  = fmaf(x.x, sW1c[ch + 3],      sb1c[ch + 3]);
            t  = fmaf(x.y, sW1c[16 + ch + 3], t);
            t  = fmaf(x.z, sW1c[32 + ch + 3], t);
            y3 = fmaf(x.w, sW1c[48 + ch + 3], t);
        }
        // variance over all 16 channels: quad reduction (quad-local mask —
        // n is uniform within the quad, so partners are converged)
        float var = y0 * y0;
        var = fmaf(y1, y1, var);
        var = fmaf(y2, y2, var);
        var = fmaf(y3, y3, var);
        var += __shfl_xor_sync(QMASK, var, 1);
        var += __shfl_xor_sync(QMASK, var, 2);
        const float inv = rsqrtf(fmaf(var, 0.0625f, 1e-5f));

        acc0 += fmaxf(fmaf(y0 * inv, sg1[ch + 0], sbe1[ch + 0]), 0.f);
        acc1 += fmaxf(fmaf(y1 * inv, sg1[ch + 1], sbe1[ch + 1]), 0.f);
        acc2 += fmaxf(fmaf(y2 * inv, sg1[ch + 2], sbe1[ch + 2]), 0.f);
        acc3 += fmaxf(fmaf(y3 * inv, sg1[ch + 3], sbe1[ch + 3]), 0.f);

        x = xn;
    }

    // Second linear with centered weights: x2 = acc @ W2c + n*b2c (mean-free).
    // Gather the 16 acc values across the quad with shuffles (all lanes have
    // exited the loop and reconverged here; sources are quad-local).
    const float fn = (float)n;
    float x2[4];
#pragma unroll
    for (int i = 0; i < 4; i++) x2[i] = fn * sb2c[ch + i];

#pragma unroll
    for (int r = 0; r < 4; r++) {
        const int src = quadbase + r;
        const float a0 = __shfl_sync(0xffffffffu, acc0, src);
        const float a1 = __shfl_sync(0xffffffffu, acc1, src);
        const float a2 = __shfl_sync(0xffffffffu, acc2, src);
        const float a3 = __shfl_sync(0xffffffffu, acc3, src);
        const int j = r * 4;
#pragma unroll
        for (int i = 0; i < 4; i++) {
            float t = x2[i];
            t = fmaf(a0, sW2c[(j + 0) * 16 + ch + i], t);
            t = fmaf(a1, sW2c[(j + 1) * 16 + ch + i], t);
            t = fmaf(a2, sW2c[(j + 2) * 16 + ch + i], t);
            t = fmaf(a3, sW2c[(j + 3) * 16 + ch + i], t);
            x2[i] = t;
        }
    }

    // Final layernorm variance across the quad.
    float var = x2[0] * x2[0];
    var = fmaf(x2[1], x2[1], var);
    var = fmaf(x2[2], x2[2], var);
    var = fmaf(x2[3], x2[3], var);
    var += __shfl_xor_sync(0xffffffffu, var, 1);
    var += __shfl_xor_sync(0xffffffffu, var, 2);
    const float inv = rsqrtf(fmaf(var, 0.0625f, 1e-5f));

    // Scatter destination (mode='drop': per-dim bounds checks).
    long flat;
    bool ok = live;
    if (p_gh != nullptr) {
        const int GH = *p_gh, GW = *p_gw, GZ = *p_gz;
        const int4 c = reinterpret_cast<const int4*>(coords)[v];
        const long B = out_elems / ((long)GH * GW * GZ * 16);
        ok = ok && (c.x >= 0 && c.x < B && c.y >= 0 && c.y < GH &&
                    c.z >= 0 && c.z < GW && c.w >= 0 && c.w < GZ);
        flat = (((long)c.x * GH + c.y) * GW + c.z) * (long)GZ + c.w;
    } else {
        flat = (long)v * stride_fallback;
    }
    const long off = flat * 16;
    if (off < 0 || off + 16 > out_elems) ok = false;

    if (ok) {
        float4 r;
        r.x = fmaf(x2[0] * inv, sg2[ch + 0], sbe2[ch + 0]);
        r.y = fmaf(x2[1] * inv, sg2[ch + 1], sbe2[ch + 1]);
        r.z = fmaf(x2[2] * inv, sg2[ch + 2], sbe2[ch + 2]);
        r.w = fmaf(x2[3] * inv, sg2[ch + 3], sbe2[ch + 3]);
        *reinterpret_cast<float4*>(out + off + ch) = r;
    }
}

extern "C" void kernel_launch(void* const* d_in, const int* in_sizes, int n_in,
                              void* d_out, int out_size)
{
    // metadata order: features, num_points, coords, W1, b1, g1, be1,
    //                 W2, b2, g2, be2, batch_size, grid_h, grid_w, grid_z
    const float* features   = (const float*)d_in[0];
    const int*   num_points = (const int*)  d_in[1];
    const int*   coords     = (const int*)  d_in[2];
    const float* W1  = (const float*)d_in[3];
    const float* b1  = (const float*)d_in[4];
    const float* g1  = (const float*)d_in[5];
    const float* be1 = (const float*)d_in[6];
    const float* W2  = (const float*)d_in[7];
    const float* b2  = (const float*)d_in[8];
    const float* g2  = (const float*)d_in[9];
    const float* be2 = (const float*)d_in[10];

    const int* p_gh = nullptr;
    const int* p_gw = nullptr;
    const int* p_gz = nullptr;
    if (n_in >= 15) {
        p_gh = (const int*)d_in[12];
        p_gw = (const int*)d_in[13];
        p_gz = (const int*)d_in[14];
    }

    const int V  = in_sizes[1];                 // num_points length
    const int H  = in_sizes[4];                 // b1 length (16)
    const int IN = in_sizes[3] / H;             // W1 rows (4)
    const int P  = (in_sizes[0] / V) / IN;      // points per voxel (32)

    float* out = (float*)d_out;
    const long out_elems = (long)out_size;
    const long stride_fallback = (out_elems / 16) / (long)V;

    // 1) Zero the dense output: driver memset (graph-capturable memset node).
    cudaMemsetAsync(d_out, 0, (size_t)out_size * sizeof(float));

    // 2) Quad-per-voxel MLP + direct scatter (ordered after memset on stream).
    const int blocks = (V + 63) / 64;           // 64 voxels per 256-thread block
    voxel_mlp_quad<<<blocks, 256>>>(
        features, num_points, coords,
        W1, b1, g1, be1, W2, b2, g2, be2,
        p_gh, p_gw, p_gz,
        out, V, P, out_elems, stride_fallback);
}